// round 11
// baseline (speedup 1.0000x reference)
#include <cuda_runtime.h>

#define N_NEUR   512
#define N_IN     21
#define N_IN_P   24      // padded row width (96B, float4-aligned)
#define BATCH_N  65536
#define ROWS     8       // rows 0..6 -> MUFU ex2; row 7 -> fma-pipe poly exp2
#define STEPS    20
#define GRID     304     // 2 CTAs/SM on 152 SMs (GB300)

__global__ void __launch_bounds__(512, 2)
adex_kernel(const float* __restrict__ x,
            const float* __restrict__ alpha,
            const float* __restrict__ beta,
            const float* __restrict__ delta_t,
            const float* __restrict__ w_in,
            const float* __restrict__ v_thresh,
            const float* __restrict__ v_reset,
            float* __restrict__ out)
{
    __shared__ float s_x[2][ROWS * N_IN_P];

    const int n = threadIdx.x;  // neuron index 0..511

    // ---- per-neuron parameters ----
    const float al  = alpha[n];
    const float be  = beta[n];
    const float idt = 1.0f / delta_t[n];
    const float vth = v_thresh[n];
    const float vrs = v_reset[n];

    const float L2E  = 1.4426950408889634f;       // log2(e)
    const float l2b  = log2f(be);                 // beta > 0 always
    const float a    = idt * L2E;                 // u = a*v + bb  (exp2-domain state)
    const float bb   = l2b - vth * a;
    const float Ecap = exp2f(10.0f * L2E + l2b);  // clamp value (binds only at step 1)
    const float A    = 1.0f - 0.1f * al;
    const float g    = -7.0f * al;

    // step-1 fold (v0 = 0): clamp folded into K1
    const float K1   = 0.1f * fminf(exp2f(bb), Ecap);
    const float bbK  = bb - a * K1;               // u1 = a*C + bbK
    const float bb1A = bb * (1.0f - A);           // Cp = a*C + bb1A
    const float na10 = -0.1f * a;
    const float u_th = l2b;                       // spike threshold (step 1 only)
    const float u_rs = a * vrs + bb;
    const float inv_a = 1.0f / a;
    const float nbba  = -bb * inv_a;

    // poly-exp2 constant: bits(c0), folded into the exponent construction
    const int K0i = __float_as_int(0.99992486f);

    // w_in row in registers
    float w[N_IN];
    #pragma unroll
    for (int j = 0; j < N_IN; j++) w[j] = w_in[n * N_IN + j];

    // staging assignment (loop-invariant)
    const int  sr     = n / N_IN_P;
    const int  sj     = n - sr * N_IN_P;
    const bool stager = (n < ROWS * N_IN_P);
    const bool realj  = stager && (sj < N_IN);

    const int ngroups = BATCH_N / ROWS;

    // ---- prologue: stage first group into buffer 0 ----
    {
        const int b0 = blockIdx.x * ROWS;
        if (stager)
            s_x[0][n] = realj ? x[(b0 + sr) * N_IN + sj] : 0.0f;
    }
    __syncthreads();

    int p = 0;
    for (int bg = blockIdx.x; bg < ngroups; bg += gridDim.x) {
        const int b0 = bg * ROWS;

        // ---- prefetch next group's x; consumed ~1000 instrs later ----
        float pre = 0.0f;
        {
            const int bgn = bg + gridDim.x;
            if (realj && bgn < ngroups)
                pre = x[(bgn * ROWS + sr) * N_IN + sj];
        }

        // ---- input projection + step-1 fold (u-space) ----
        float u[ROWS], Cp[ROWS];
        #pragma unroll
        for (int r = 0; r < ROWS; r++) {
            const float4* sx4 = reinterpret_cast<const float4*>(&s_x[p][r * N_IN_P]);
            float4 x0 = sx4[0], x1 = sx4[1], x2 = sx4[2];
            float4 x3 = sx4[3], x4 = sx4[4], x5 = sx4[5];
            float acc0 = w[0] * x0.x, acc1 = w[1] * x0.y;
            acc0 = fmaf(w[2],  x0.z, acc0);  acc1 = fmaf(w[3],  x0.w, acc1);
            acc0 = fmaf(w[4],  x1.x, acc0);  acc1 = fmaf(w[5],  x1.y, acc1);
            acc0 = fmaf(w[6],  x1.z, acc0);  acc1 = fmaf(w[7],  x1.w, acc1);
            acc0 = fmaf(w[8],  x2.x, acc0);  acc1 = fmaf(w[9],  x2.y, acc1);
            acc0 = fmaf(w[10], x2.z, acc0);  acc1 = fmaf(w[11], x2.w, acc1);
            acc0 = fmaf(w[12], x3.x, acc0);  acc1 = fmaf(w[13], x3.y, acc1);
            acc0 = fmaf(w[14], x3.z, acc0);  acc1 = fmaf(w[15], x3.w, acc1);
            acc0 = fmaf(w[16], x4.x, acc0);  acc1 = fmaf(w[17], x4.y, acc1);
            acc0 = fmaf(w[18], x4.z, acc0);  acc1 = fmaf(w[19], x4.w, acc1);
            acc0 = fmaf(w[20], x5.x, acc0);
            const float C = fmaf(0.1f, acc0 + acc1, g);
            Cp[r] = fmaf(a, C, bb1A);
            float u1 = fmaf(a, C, bbK);          // step 1 (clamp folded)
            u[r] = (u1 > u_th) ? u_rs : u1;      // the only possible spike
        }

        // ---- steps 2..20 ----
        // spike check + clamp provably dead after step 1 (round-6 proof).
        // Rows 0..6: MUFU ex2 (ftz flushes 2^u for u << -126 to 0 natively).
        // Row 7: polynomial exp2 on the fma/alu pipes. Its exponent-build
        // wraps for u < -126 (the round-9/10 NaN), so clamp the POLY INPUT
        // only: for u <= -60, 2^u < 9e-19 contributes nothing to the update,
        // while the state u itself stays unclamped (matches reference decay).
        #pragma unroll
        for (int s = 1; s < STEPS; s++) {
            #pragma unroll
            for (int r = 0; r < ROWS - 1; r++) {
                float e;
                asm("ex2.approx.ftz.f32 %0, %1;" : "=f"(e) : "f"(u[r]));
                float t = fmaf(na10, e, Cp[r]);
                u[r] = fmaf(A, u[r], t);
            }
            {   // row 7: poly exp2, input clamped to [-60, 0]
                float uu = u[ROWS - 1];
                float up = fmaxf(uu, -60.0f);           // FMNMX, alu pipe (idle)
                float y  = up + 12582912.0f;            // n = rn(up), magic add
                float nf = y - 12582912.0f;             // exact (Sterbenz)
                float f  = up - nf;                     // exact, f in [-0.5, 0.5]
                float q  = fmaf(0.05550411f, f, 0.24263101f);
                q = fmaf(q, f, 0.69314718f);
                // sc = c0 * 2^n  via one LEA: (bits(y)<<23) + bits(c0)
                float sc = __int_as_float((__float_as_int(y) << 23) + K0i);
                float e  = fmaf(sc * f, q, sc);         // sc*(1 + f*q)
                float t  = fmaf(na10, e, Cp[ROWS - 1]);
                u[ROWS - 1] = fmaf(A, uu, t);           // state uses UNCLAMPED uu
            }
        }

        // ---- convert u -> v and store (coalesced STG.32) ----
        {
            float* ob = out + b0 * N_NEUR + n;
            #pragma unroll
            for (int r = 0; r < ROWS; r++)
                ob[r * N_NEUR] = fmaf(u[r], inv_a, nbba);
        }

        // ---- publish next group's x; single barrier per group ----
        if (stager) s_x[p ^ 1][n] = pre;
        __syncthreads();
        p ^= 1;
    }
}

extern "C" void kernel_launch(void* const* d_in, const int* in_sizes, int n_in,
                              void* d_out, int out_size)
{
    const float* x        = (const float*)d_in[0];
    const float* alpha    = (const float*)d_in[1];
    const float* beta     = (const float*)d_in[2];
    const float* delta_t  = (const float*)d_in[3];
    const float* w_in     = (const float*)d_in[4];
    const float* v_thresh = (const float*)d_in[5];
    const float* v_reset  = (const float*)d_in[6];
    float* out = (float*)d_out;

    adex_kernel<<<GRID, 512>>>(x, alpha, beta, delta_t, w_in, v_thresh, v_reset, out);
}

// round 13
// speedup vs baseline: 1.7604x; 1.7604x over previous
#include <cuda_runtime.h>

#define N_NEUR   512
#define N_IN     21
#define N_IN_P   24      // padded row width (96B, float4-aligned)
#define BATCH_N  65536
#define ROWS     8       // rows 0..6 -> MUFU ex2; row 7 -> fma-pipe poly exp2
#define STEPS    20
#define GRID     304     // 2 CTAs/SM on 152 SMs (GB300)

__global__ void __launch_bounds__(512, 2)
adex_kernel(const float* __restrict__ x,
            const float* __restrict__ alpha,
            const float* __restrict__ beta,
            const float* __restrict__ delta_t,
            const float* __restrict__ w_in,
            const float* __restrict__ v_thresh,
            const float* __restrict__ v_reset,
            float* __restrict__ out)
{
    __shared__ float s_x[2][ROWS * N_IN_P];

    const int n = threadIdx.x;  // neuron index 0..511

    // ---- per-neuron parameters ----
    const float al  = alpha[n];
    const float be  = beta[n];
    const float idt = 1.0f / delta_t[n];
    const float vth = v_thresh[n];
    const float vrs = v_reset[n];

    const float L2E  = 1.4426950408889634f;       // log2(e)
    const float l2b  = log2f(be);                 // beta > 0 always
    const float a    = idt * L2E;                 // u = a*v + bb  (exp2-domain state)
    const float bb   = l2b - vth * a;
    const float Ecap = exp2f(10.0f * L2E + l2b);  // clamp value (binds only at step 1)
    const float A    = 1.0f - 0.1f * al;
    const float g    = -7.0f * al;

    // step-1 fold (v0 = 0): clamp folded into K1
    const float K1   = 0.1f * fminf(exp2f(bb), Ecap);
    const float bbK  = bb - a * K1;               // u1 = a*C + bbK
    const float bb1A = bb * (1.0f - A);           // Cp = a*C + bb1A
    const float na10 = -0.1f * a;
    const float u_th = l2b;                       // spike threshold (step 1 only)
    const float u_rs = a * vrs + bb;
    const float inv_a = 1.0f / a;
    const float nbba  = -bb * inv_a;

    // poly-exp2 constant: bits(c0), folded into the exponent construction
    const int K0i = __float_as_int(0.99992486f);

    // w_in row in registers
    float w[N_IN];
    #pragma unroll
    for (int j = 0; j < N_IN; j++) w[j] = w_in[n * N_IN + j];

    // staging assignment (loop-invariant)
    const int  sr     = n / N_IN_P;
    const int  sj     = n - sr * N_IN_P;
    const bool stager = (n < ROWS * N_IN_P);
    const bool realj  = stager && (sj < N_IN);

    const int ngroups = BATCH_N / ROWS;

    // ---- prologue: stage first group into buffer 0 ----
    {
        const int b0 = blockIdx.x * ROWS;
        if (stager)
            s_x[0][n] = realj ? x[(b0 + sr) * N_IN + sj] : 0.0f;
    }
    __syncthreads();

    int p = 0;
    for (int bg = blockIdx.x; bg < ngroups; bg += gridDim.x) {
        const int b0 = bg * ROWS;

        // ---- prefetch next group's x; consumed ~1000 instrs later ----
        float pre = 0.0f;
        {
            const int bgn = bg + gridDim.x;
            if (realj && bgn < ngroups)
                pre = x[(bgn * ROWS + sr) * N_IN + sj];
        }

        // ---- input projection, q-OUTER to cap register pressure ----
        // Only ONE float4 of x is live at a time (4 regs vs 24 in the
        // round-6 row-inner form). Same LDS.128 broadcast count (48).
        float acc0[ROWS], acc1[ROWS];
        #pragma unroll
        for (int r = 0; r < ROWS; r++) { acc0[r] = 0.0f; acc1[r] = 0.0f; }
        #pragma unroll
        for (int q = 0; q < N_IN_P / 4; q++) {
            #pragma unroll
            for (int r = 0; r < ROWS; r++) {
                float4 xx = reinterpret_cast<const float4*>(
                                &s_x[p][r * N_IN_P])[q];
                if (q < 5) {
                    acc0[r] = fmaf(w[4 * q + 0], xx.x, acc0[r]);
                    acc1[r] = fmaf(w[4 * q + 1], xx.y, acc1[r]);
                    acc0[r] = fmaf(w[4 * q + 2], xx.z, acc0[r]);
                    acc1[r] = fmaf(w[4 * q + 3], xx.w, acc1[r]);
                } else {
                    acc0[r] = fmaf(w[20], xx.x, acc0[r]);  // j=21..23 are pad
                }
            }
        }

        // ---- fold dot -> step-1 (u-space) ----
        float u[ROWS], Cp[ROWS];
        #pragma unroll
        for (int r = 0; r < ROWS; r++) {
            const float C = fmaf(0.1f, acc0[r] + acc1[r], g);
            Cp[r] = fmaf(a, C, bb1A);
            float u1 = fmaf(a, C, bbK);          // step 1 (clamp folded)
            u[r] = (u1 > u_th) ? u_rs : u1;      // the only possible spike
        }

        // ---- steps 2..20 ----
        // spike + clamp provably dead after step 1 (round-6 proof).
        // Rows 0..6: MUFU ex2 (ftz flushes deep-negative u to 0 natively).
        // Row 7: poly exp2 on fma/alu pipes; POLY INPUT clamped to [-60,0]
        // (2^u < 9e-19 there, contributes nothing; state stays unclamped).
        #pragma unroll
        for (int s = 1; s < STEPS; s++) {
            #pragma unroll
            for (int r = 0; r < ROWS - 1; r++) {
                float e;
                asm("ex2.approx.ftz.f32 %0, %1;" : "=f"(e) : "f"(u[r]));
                float t = fmaf(na10, e, Cp[r]);
                u[r] = fmaf(A, u[r], t);
            }
            {   // row 7: poly exp2
                float uu = u[ROWS - 1];
                float up = fmaxf(uu, -60.0f);           // FMNMX (alu pipe)
                float y  = up + 12582912.0f;            // n = rn(up), magic add
                float nf = y - 12582912.0f;             // exact (Sterbenz)
                float f  = up - nf;                     // exact, f in [-0.5, 0.5]
                float q  = fmaf(0.05550411f, f, 0.24263101f);
                q = fmaf(q, f, 0.69314718f);
                // sc = c0 * 2^n  via one LEA: (bits(y)<<23) + bits(c0)
                float sc = __int_as_float((__float_as_int(y) << 23) + K0i);
                float e  = fmaf(sc * f, q, sc);         // sc*(1 + f*q)
                float t  = fmaf(na10, e, Cp[ROWS - 1]);
                u[ROWS - 1] = fmaf(A, uu, t);           // state uses UNCLAMPED uu
            }
        }

        // ---- convert u -> v and store (coalesced STG.32) ----
        {
            float* ob = out + b0 * N_NEUR + n;
            #pragma unroll
            for (int r = 0; r < ROWS; r++)
                ob[r * N_NEUR] = fmaf(u[r], inv_a, nbba);
        }

        // ---- publish next group's x; single barrier per group ----
        if (stager) s_x[p ^ 1][n] = pre;
        __syncthreads();
        p ^= 1;
    }
}

extern "C" void kernel_launch(void* const* d_in, const int* in_sizes, int n_in,
                              void* d_out, int out_size)
{
    const float* x        = (const float*)d_in[0];
    const float* alpha    = (const float*)d_in[1];
    const float* beta     = (const float*)d_in[2];
    const float* delta_t  = (const float*)d_in[3];
    const float* w_in     = (const float*)d_in[4];
    const float* v_thresh = (const float*)d_in[5];
    const float* v_reset  = (const float*)d_in[6];
    float* out = (float*)d_out;

    adex_kernel<<<GRID, 512>>>(x, alpha, beta, delta_t, w_in, v_thresh, v_reset, out);
}

// round 16
// speedup vs baseline: 1.8260x; 1.0373x over previous
#include <cuda_runtime.h>

#define N_NEUR   512
#define N_IN     21
#define N_IN_P   24      // padded row width (96B, float4-aligned)
#define BATCH_N  65536
#define ROWS     8
#define NPAIR    (ROWS / 2)
#define STEPS    20
#define GRID     304     // 2 CTAs/SM on 152 SMs (GB300)

typedef unsigned long long u64;

static __device__ __forceinline__ u64 pack2(float lo, float hi) {
    u64 r; asm("mov.b64 %0, {%1, %2};" : "=l"(r) : "f"(lo), "f"(hi)); return r;
}
static __device__ __forceinline__ void unpack2(u64 p, float& lo, float& hi) {
    asm("mov.b64 {%0, %1}, %2;" : "=f"(lo), "=f"(hi) : "l"(p));
}
static __device__ __forceinline__ u64 f2fma(u64 a, u64 b, u64 c) {
    u64 d; asm("fma.rn.f32x2 %0, %1, %2, %3;" : "=l"(d) : "l"(a), "l"(b), "l"(c)); return d;
}

// Dual exp2 via ONE MUFU op: f32 pair -> bf16x2 -> ex2 -> f32 pair.
// cvt = F2FP (fma-class, rt2); unpack = SHL/AND on the idle alu pipe
// (bf16 -> f32 is a pure bit shift). ftz flushes 2^u for deep-negative u
// to 0, exactly like the scalar f32 path.
static __device__ __forceinline__ u64 ex2_bf16x2(u64 u2) {
    u64 e2;
    asm("{\n\t"
        ".reg .b32 lo, hi, b, el, eh;\n\t"
        "mov.b64 {lo, hi}, %1;\n\t"
        "cvt.rn.bf16x2.f32 b, hi, lo;\n\t"    // first src -> upper half
        "ex2.approx.ftz.bf16x2 b, b;\n\t"     // one MUFU pass, two exps
        "shl.b32 el, b, 16;\n\t"              // lo bf16 -> f32 bits
        "and.b32 eh, b, 0xFFFF0000;\n\t"      // hi bf16 -> f32 bits
        "mov.b64 %0, {el, eh};\n\t"
        "}" : "=l"(e2) : "l"(u2));
    return e2;
}

__global__ void __launch_bounds__(512, 2)
adex_kernel(const float* __restrict__ x,
            const float* __restrict__ alpha,
            const float* __restrict__ beta,
            const float* __restrict__ delta_t,
            const float* __restrict__ w_in,
            const float* __restrict__ v_thresh,
            const float* __restrict__ v_reset,
            float* __restrict__ out)
{
    __shared__ float s_x[2][ROWS * N_IN_P];

    const int n = threadIdx.x;  // neuron index 0..511

    // ---- per-neuron parameters ----
    const float al  = alpha[n];
    const float be  = beta[n];
    const float idt = 1.0f / delta_t[n];
    const float vth = v_thresh[n];
    const float vrs = v_reset[n];

    const float L2E  = 1.4426950408889634f;       // log2(e)
    const float l2b  = log2f(be);                 // beta > 0 always
    const float a    = idt * L2E;                 // u = a*v + bb  (exp2-domain state)
    const float bb   = l2b - vth * a;
    const float Ecap = exp2f(10.0f * L2E + l2b);  // clamp value (binds only at step 1)
    const float A    = 1.0f - 0.1f * al;
    const float g    = -7.0f * al;

    // step-1 fold (v0 = 0): clamp folded into K1
    const float K1   = 0.1f * fminf(exp2f(bb), Ecap);
    const float bbK  = bb - a * K1;               // u1 = a*C + bbK
    const float bb1A = bb * (1.0f - A);           // Cp = a*C + bb1A
    const float na10 = -0.1f * a;
    const float u_th = l2b;                       // spike threshold (step 1 only)
    const float u_rs = a * vrs + bb;
    const float inv_a = 1.0f / a;
    const float nbba  = -bb * inv_a;

    // packed per-neuron step constants
    const u64 A2  = pack2(A, A);
    const u64 na2 = pack2(na10, na10);

    // w_in row in registers
    float w[N_IN];
    #pragma unroll
    for (int j = 0; j < N_IN; j++) w[j] = w_in[n * N_IN + j];

    // staging assignment (loop-invariant)
    const int  sr     = n / N_IN_P;
    const int  sj     = n - sr * N_IN_P;
    const bool stager = (n < ROWS * N_IN_P);
    const bool realj  = stager && (sj < N_IN);

    const int ngroups = BATCH_N / ROWS;

    // ---- prologue: stage first group into buffer 0 ----
    {
        const int b0 = blockIdx.x * ROWS;
        if (stager)
            s_x[0][n] = realj ? x[(b0 + sr) * N_IN + sj] : 0.0f;
    }
    __syncthreads();

    int p = 0;
    for (int bg = blockIdx.x; bg < ngroups; bg += gridDim.x) {
        const int b0 = bg * ROWS;

        // ---- prefetch next group's x; consumed ~1000 instrs later ----
        float pre = 0.0f;
        {
            const int bgn = bg + gridDim.x;
            if (realj && bgn < ngroups)
                pre = x[(bgn * ROWS + sr) * N_IN + sj];
        }

        // ---- input projection + step-1 fold (round-6 form, known good) ----
        u64 u2[NPAIR], Cp2[NPAIR];
        #pragma unroll
        for (int pr = 0; pr < NPAIR; pr++) {
            float us[2], cps[2];
            #pragma unroll
            for (int h = 0; h < 2; h++) {
                const int r = 2 * pr + h;
                const float4* sx4 = reinterpret_cast<const float4*>(&s_x[p][r * N_IN_P]);
                float4 x0 = sx4[0], x1 = sx4[1], x2 = sx4[2];
                float4 x3 = sx4[3], x4 = sx4[4], x5 = sx4[5];
                float acc0 = w[0] * x0.x, acc1 = w[1] * x0.y;
                acc0 = fmaf(w[2],  x0.z, acc0);  acc1 = fmaf(w[3],  x0.w, acc1);
                acc0 = fmaf(w[4],  x1.x, acc0);  acc1 = fmaf(w[5],  x1.y, acc1);
                acc0 = fmaf(w[6],  x1.z, acc0);  acc1 = fmaf(w[7],  x1.w, acc1);
                acc0 = fmaf(w[8],  x2.x, acc0);  acc1 = fmaf(w[9],  x2.y, acc1);
                acc0 = fmaf(w[10], x2.z, acc0);  acc1 = fmaf(w[11], x2.w, acc1);
                acc0 = fmaf(w[12], x3.x, acc0);  acc1 = fmaf(w[13], x3.y, acc1);
                acc0 = fmaf(w[14], x3.z, acc0);  acc1 = fmaf(w[15], x3.w, acc1);
                acc0 = fmaf(w[16], x4.x, acc0);  acc1 = fmaf(w[17], x4.y, acc1);
                acc0 = fmaf(w[18], x4.z, acc0);  acc1 = fmaf(w[19], x4.w, acc1);
                acc0 = fmaf(w[20], x5.x, acc0);
                const float C = fmaf(0.1f, acc0 + acc1, g);
                cps[h] = fmaf(a, C, bb1A);
                float u1 = fmaf(a, C, bbK);        // step 1 (clamp folded)
                us[h] = (u1 > u_th) ? u_rs : u1;   // the only possible spike
            }
            u2[pr]  = pack2(us[0], us[1]);
            Cp2[pr] = pack2(cps[0], cps[1]);
        }

        // ---- steps 2..20: packed pairs ----
        // spike + clamp provably dead after step 1 (round-6 proof).
        // Per pair-step: 1 CVT + 1 MUFU(bf16x2, dual exp) + 2 ALU + 2 FFMA2.
        #pragma unroll
        for (int s = 1; s < STEPS; s++) {
            #pragma unroll
            for (int pr = 0; pr < NPAIR; pr++) {
                u64 e2 = ex2_bf16x2(u2[pr]);
                u64 t  = f2fma(na2, e2, Cp2[pr]);
                u2[pr] = f2fma(A2, u2[pr], t);
            }
        }

        // ---- convert u -> v and store (coalesced STG.32) ----
        {
            float* ob = out + b0 * N_NEUR + n;
            #pragma unroll
            for (int pr = 0; pr < NPAIR; pr++) {
                float ua, ub; unpack2(u2[pr], ua, ub);
                ob[(2 * pr + 0) * N_NEUR] = fmaf(ua, inv_a, nbba);
                ob[(2 * pr + 1) * N_NEUR] = fmaf(ub, inv_a, nbba);
            }
        }

        // ---- publish next group's x; single barrier per group ----
        if (stager) s_x[p ^ 1][n] = pre;
        __syncthreads();
        p ^= 1;
    }
}

extern "C" void kernel_launch(void* const* d_in, const int* in_sizes, int n_in,
                              void* d_out, int out_size)
{
    const float* x        = (const float*)d_in[0];
    const float* alpha    = (const float*)d_in[1];
    const float* beta     = (const float*)d_in[2];
    const float* delta_t  = (const float*)d_in[3];
    const float* w_in     = (const float*)d_in[4];
    const float* v_thresh = (const float*)d_in[5];
    const float* v_reset  = (const float*)d_in[6];
    float* out = (float*)d_out;

    adex_kernel<<<GRID, 512>>>(x, alpha, beta, delta_t, w_in, v_thresh, v_reset, out);
}